// round 9
// baseline (speedup 1.0000x reference)
#include <cuda_runtime.h>
#include <stdint.h>

// Problem constants
#define NUM_STEPS 25
#define BATCH     4096
#define NIN       784
#define NHID      1000
#define NOUT      10
#define MTOT      (NUM_STEPS * BATCH)   // 102400
#define BETA      0.95f
#define THRESH    1.0f

// Rigorous fused-vs-unfused chain error coefficient:
// |accF - accU| <= 2^-24 * (2*784 + 1) * S, S >= sum_k |a_k b_k|  (Cauchy-Schwarz)
// 1569 * 2^-24 = 9.35e-5; padded for norm/arith slop.
#define ERRC 1.2e-4f

// Scratch (device globals; no runtime allocation allowed)
__device__ float    g_cur1[(size_t)MTOT * NHID];     // [t*B+b][h] (approx; patched exact where flagged)
__device__ uint32_t g_maskT[(size_t)32 * MTOT];      // spk1 bits, [word][row]
__device__ float    g_cur2[(size_t)MTOT * NOUT];     // [t*B+b][o]
__device__ float    g_xn[MTOT];                      // ||X row|| upper bounds
__device__ float    g_wn[1024];                      // ||W1 row|| upper bounds
__device__ uint32_t g_flag[BATCH * 32];              // chain-uncertain bitmask [b][chunk]

// ---------------------------------------------------------------------------
// Norm kernels: rigorous upper bounds on row 2-norms (x1.0002 slop factor).
// ---------------------------------------------------------------------------
__global__ void __launch_bounds__(256)
xnorm_kernel(const float* __restrict__ X)
{
    const int m    = blockIdx.x * 8 + (threadIdx.x >> 5);
    const int lane = threadIdx.x & 31;
    if (m >= MTOT) return;
    float s = 0.f;
    for (int k = lane; k < NIN; k += 32) {
        const float v = X[(size_t)m * NIN + k];
        s = fmaf(v, v, s);
    }
#pragma unroll
    for (int d = 16; d > 0; d >>= 1) s += __shfl_xor_sync(0xffffffffu, s, d);
    if (lane == 0) g_xn[m] = sqrtf(s) * 1.0002f;
}

__global__ void __launch_bounds__(256)
wnorm_kernel(const float* __restrict__ W1)
{
    const int h    = blockIdx.x * 8 + (threadIdx.x >> 5);
    const int lane = threadIdx.x & 31;
    if (h >= 1024) return;
    float s = 0.f;
    if (h < NHID)
        for (int k = lane; k < NIN; k += 32) {
            const float v = W1[(size_t)h * NIN + k];
            s = fmaf(v, v, s);
        }
#pragma unroll
    for (int d = 16; d > 0; d >>= 1) s += __shfl_xor_sync(0xffffffffu, s, d);
    if (lane == 0) g_wn[h] = sqrtf(s) * 1.0002f;
}

// ---------------------------------------------------------------------------
// Kernel 1: APPROX cur1 = X @ W1^T + b1 via FUSED FFMA chain (same ascending
// order as reference; 1 instr/MAC). Double-buffered 128x128x16 tile.
// ---------------------------------------------------------------------------
#define BM 128
#define BN 128
#define BK 16
#define NT (NIN / BK)     // 49 k-tiles
#define LDA (BM + 4)
#define LDB (BN + 4)

__global__ void __launch_bounds__(256, 2)
gemm1f_kernel(const float* __restrict__ X, const float* __restrict__ W1,
              const float* __restrict__ b1)
{
    __shared__ float As[2][BK * LDA];
    __shared__ float Bs[2][BK * LDB];

    const int tid = threadIdx.x;
    const int bm  = blockIdx.y * BM;
    const int bn  = blockIdx.x * BN;

    const int lr  = tid >> 2;
    const int lc4 = (tid & 3) * 4;

    const int tx   = tid & 15;
    const int ty   = tid >> 4;
    const int row0 = ty * 8;
    const int col0 = tx * 8;

    const float* Xp0 = X  + (size_t)(bm + lr) * NIN + lc4;
    const float* Xp1 = X  + (size_t)(bm + lr + 64) * NIN + lc4;
    const int    n0  = bn + lr;
    const int    n1  = bn + lr + 64;
    const float* Wp0 = W1 + (size_t)n0 * NIN + lc4;
    const float* Wp1 = W1 + (size_t)n1 * NIN + lc4;
    const bool   v0  = (n0 < NHID);
    const bool   v1  = (n1 < NHID);

    float acc[8][8];
#pragma unroll
    for (int i = 0; i < 8; i++)
#pragma unroll
        for (int j = 0; j < 8; j++) acc[i][j] = 0.f;

    float4 pa0, pa1, pb0, pb1;

    pa0 = *(const float4*)(Xp0);
    pa1 = *(const float4*)(Xp1);
    pb0 = v0 ? *(const float4*)(Wp0) : make_float4(0.f, 0.f, 0.f, 0.f);
    pb1 = v1 ? *(const float4*)(Wp1) : make_float4(0.f, 0.f, 0.f, 0.f);
    {
        float* as = As[0]; float* bs = Bs[0];
        as[(lc4 + 0) * LDA + lr]      = pa0.x;
        as[(lc4 + 1) * LDA + lr]      = pa0.y;
        as[(lc4 + 2) * LDA + lr]      = pa0.z;
        as[(lc4 + 3) * LDA + lr]      = pa0.w;
        as[(lc4 + 0) * LDA + lr + 64] = pa1.x;
        as[(lc4 + 1) * LDA + lr + 64] = pa1.y;
        as[(lc4 + 2) * LDA + lr + 64] = pa1.z;
        as[(lc4 + 3) * LDA + lr + 64] = pa1.w;
        bs[(lc4 + 0) * LDB + lr]      = pb0.x;
        bs[(lc4 + 1) * LDB + lr]      = pb0.y;
        bs[(lc4 + 2) * LDB + lr]      = pb0.z;
        bs[(lc4 + 3) * LDB + lr]      = pb0.w;
        bs[(lc4 + 0) * LDB + lr + 64] = pb1.x;
        bs[(lc4 + 1) * LDB + lr + 64] = pb1.y;
        bs[(lc4 + 2) * LDB + lr + 64] = pb1.z;
        bs[(lc4 + 3) * LDB + lr + 64] = pb1.w;
    }
    __syncthreads();

#pragma unroll 1
    for (int kt = 0; kt < NT; kt++) {
        const int cur = kt & 1;

        if (kt + 1 < NT) {
            const int koff = (kt + 1) * BK;
            pa0 = *(const float4*)(Xp0 + koff);
            pa1 = *(const float4*)(Xp1 + koff);
            pb0 = v0 ? *(const float4*)(Wp0 + koff) : make_float4(0.f, 0.f, 0.f, 0.f);
            pb1 = v1 ? *(const float4*)(Wp1 + koff) : make_float4(0.f, 0.f, 0.f, 0.f);
        }

        const float* as = As[cur];
        const float* bs = Bs[cur];
#pragma unroll
        for (int k = 0; k < BK; k++) {
            float a[8], b[8];
            *(float4*)(a)     = *(const float4*)&as[k * LDA + row0];
            *(float4*)(a + 4) = *(const float4*)&as[k * LDA + row0 + 4];
            *(float4*)(b)     = *(const float4*)&bs[k * LDB + col0];
            *(float4*)(b + 4) = *(const float4*)&bs[k * LDB + col0 + 4];
#pragma unroll
            for (int i = 0; i < 8; i++)
#pragma unroll
                for (int j = 0; j < 8; j++)
                    acc[i][j] = __fmaf_rn(a[i], b[j], acc[i][j]);
        }

        if (kt + 1 < NT) {
            const int nxt = (kt + 1) & 1;
            float* asn = As[nxt]; float* bsn = Bs[nxt];
            asn[(lc4 + 0) * LDA + lr]      = pa0.x;
            asn[(lc4 + 1) * LDA + lr]      = pa0.y;
            asn[(lc4 + 2) * LDA + lr]      = pa0.z;
            asn[(lc4 + 3) * LDA + lr]      = pa0.w;
            asn[(lc4 + 0) * LDA + lr + 64] = pa1.x;
            asn[(lc4 + 1) * LDA + lr + 64] = pa1.y;
            asn[(lc4 + 2) * LDA + lr + 64] = pa1.z;
            asn[(lc4 + 3) * LDA + lr + 64] = pa1.w;
            bsn[(lc4 + 0) * LDB + lr]      = pb0.x;
            bsn[(lc4 + 1) * LDB + lr]      = pb0.y;
            bsn[(lc4 + 2) * LDB + lr]      = pb0.z;
            bsn[(lc4 + 3) * LDB + lr]      = pb0.w;
            bsn[(lc4 + 0) * LDB + lr + 64] = pb1.x;
            bsn[(lc4 + 1) * LDB + lr + 64] = pb1.y;
            bsn[(lc4 + 2) * LDB + lr + 64] = pb1.z;
            bsn[(lc4 + 3) * LDB + lr + 64] = pb1.w;
            __syncthreads();
        }
    }

#pragma unroll
    for (int i = 0; i < 8; i++) {
        const int m = bm + row0 + i;
#pragma unroll
        for (int j = 0; j < 8; j++) {
            const int n = bn + col0 + j;
            if (n < NHID)
                g_cur1[(size_t)m * NHID + n] = __fadd_rn(acc[i][j], __ldg(&b1[n]));
        }
    }
}

// ---------------------------------------------------------------------------
// Flag kernel: interval recurrence over approx cur1. Flags any chain whose
// spike/reset sign decision is uncertain within the rigorous error radius.
// ---------------------------------------------------------------------------
__global__ void __launch_bounds__(256)
flag_kernel()
{
    const int warp  = (blockIdx.x * blockDim.x + threadIdx.x) >> 5;
    const int lane  = threadIdx.x & 31;
    const int chunk = warp & 31;
    const int b     = warp >> 5;
    if (b >= BATCH) return;

    const int h = chunk * 32 + lane;
    const bool valid = (h < NHID);
    const float wn = valid ? g_wn[h] : 0.f;

    float mem = 0.f, e = 0.f;
    bool flg = false;
#pragma unroll
    for (int t = 0; t < NUM_STEPS; t++) {
        const float c = valid ? g_cur1[((size_t)t * BATCH + b) * NHID + h] : -1.f;
        const float rst = (mem > THRESH) ? THRESH : 0.f;
        mem = __fsub_rn(__fadd_rn(__fmul_rn(BETA, mem), c), rst);
        const float delta = ERRC * g_xn[t * BATCH + b] * wn;
        e = BETA * e + delta + 2e-7f * (fabsf(mem) + fabsf(c) + 2.f);
        flg = flg || (valid && fabsf(mem - THRESH) <= e);
    }
    const uint32_t w = __ballot_sync(0xffffffffu, flg);
    if (lane == 0) g_flag[b * 32 + chunk] = w;
}

// ---------------------------------------------------------------------------
// Fixup kernel: recompute EXACT unfused ascending chain (cur1) for flagged
// (b,h) chains, all t. CTA per b; warp handles (t, group of 32 flagged h).
// X row broadcast per warp; W1 rows L1-reused across the 25 t's.
// ---------------------------------------------------------------------------
__global__ void __launch_bounds__(256)
fixup_kernel(const float* __restrict__ X, const float* __restrict__ W1,
             const float* __restrict__ b1)
{
    __shared__ unsigned short list[1024];
    __shared__ int cnt;
    const int b   = blockIdx.x;
    const int tid = threadIdx.x;
    if (tid == 0) cnt = 0;
    __syncthreads();

    for (int h = tid; h < NHID; h += 256) {
        if ((g_flag[b * 32 + (h >> 5)] >> (h & 31)) & 1u) {
            const int idx = atomicAdd(&cnt, 1);
            list[idx] = (unsigned short)h;
        }
    }
    __syncthreads();

    const int nf = cnt;
    if (nf == 0) return;

    const int ngroups = (nf + 31) / 32;
    const int units   = ngroups * NUM_STEPS;
    const int warpid  = tid >> 5;
    const int lane    = tid & 31;

    for (int u = warpid; u < units; u += 8) {
        const int g = u / NUM_STEPS;
        const int t = u - g * NUM_STEPS;
        const int li = g * 32 + lane;
        const bool act = (li < nf);
        const int h = act ? (int)list[li] : 0;

        const float* xrow = X  + ((size_t)t * BATCH + b) * NIN;
        const float* wrow = W1 + (size_t)h * NIN;

        float acc = 0.f;
#pragma unroll 8
        for (int k = 0; k < NIN; k++)
            acc = __fadd_rn(acc, __fmul_rn(__ldg(xrow + k), wrow[k]));

        if (act)
            g_cur1[((size_t)t * BATCH + b) * NHID + h] =
                __fadd_rn(acc, __ldg(&b1[h]));
    }
}

// ---------------------------------------------------------------------------
// Kernel 2: layer-1 recurrence on patched cur1 -> spk1 transposed bitmask.
// ---------------------------------------------------------------------------
__global__ void __launch_bounds__(256)
rec1_kernel()
{
    const int warp  = (blockIdx.x * blockDim.x + threadIdx.x) >> 5;
    const int lane  = threadIdx.x & 31;
    const int chunk = warp & 31;
    const int b     = warp >> 5;
    if (b >= BATCH) return;

    const int h = chunk * 32 + lane;
    const bool valid = (h < NHID);

    float mem = 0.f;
#pragma unroll
    for (int t = 0; t < NUM_STEPS; t++) {
        const float c = valid ? g_cur1[((size_t)t * BATCH + b) * NHID + h] : -1.f;
        const float rst = (mem > THRESH) ? THRESH : 0.f;
        mem = __fsub_rn(__fadd_rn(__fmul_rn(BETA, mem), c), rst);
        const uint32_t w = __ballot_sync(0xffffffffu, mem > THRESH);
        if (lane == 0)
            g_maskT[(size_t)chunk * MTOT + (size_t)t * BATCH + b] = w;
    }
}

// ---------------------------------------------------------------------------
// Kernel 3: cur2 = spk1 @ W2^T + b2 (exact: spk in {0,1} -> fma chain is
// bit-identical to the unfused ascending chain).
// ---------------------------------------------------------------------------
#define W2LD 12

__global__ void __launch_bounds__(256)
gemm2_kernel(const float* __restrict__ W2, const float* __restrict__ b2)
{
    __shared__ float W2t[1000 * W2LD];
    for (int i = threadIdx.x; i < NOUT * NHID; i += 256) {
        const int o = i / NHID, h = i - o * NHID;
        W2t[h * W2LD + o] = W2[i];
    }
    __syncthreads();

    const int row = blockIdx.x * 256 + threadIdx.x;

    float acc[NOUT];
#pragma unroll
    for (int o = 0; o < NOUT; o++) acc[o] = 0.f;

#pragma unroll 1
    for (int wd = 0; wd < 32; wd++) {
        const uint32_t w = g_maskT[(size_t)wd * MTOT + row];
        const int nb = (wd < 31) ? 32 : (NHID - 31 * 32);
#pragma unroll 8
        for (int bit = 0; bit < nb; bit++) {
            const float f = (float)((w >> bit) & 1u);
            const int h = wd * 32 + bit;
            const float* wrow = &W2t[h * W2LD];
            float4 w0 = *(const float4*)(wrow);
            float4 w1 = *(const float4*)(wrow + 4);
            float2 w2v = *(const float2*)(wrow + 8);
            acc[0] = __fmaf_rn(f, w0.x, acc[0]);
            acc[1] = __fmaf_rn(f, w0.y, acc[1]);
            acc[2] = __fmaf_rn(f, w0.z, acc[2]);
            acc[3] = __fmaf_rn(f, w0.w, acc[3]);
            acc[4] = __fmaf_rn(f, w1.x, acc[4]);
            acc[5] = __fmaf_rn(f, w1.y, acc[5]);
            acc[6] = __fmaf_rn(f, w1.z, acc[6]);
            acc[7] = __fmaf_rn(f, w1.w, acc[7]);
            acc[8] = __fmaf_rn(f, w2v.x, acc[8]);
            acc[9] = __fmaf_rn(f, w2v.y, acc[9]);
        }
    }

    float* out = g_cur2 + (size_t)row * NOUT;
#pragma unroll
    for (int o = 0; o < NOUT; o++)
        out[o] = __fadd_rn(acc[o], __ldg(&b2[o]));
}

// ---------------------------------------------------------------------------
// Kernel 4: layer-2 recurrence + outputs [spk_rec | mem_rec].
// ---------------------------------------------------------------------------
__global__ void __launch_bounds__(256)
rec2_kernel(float* __restrict__ out)
{
    const int idx = blockIdx.x * blockDim.x + threadIdx.x;
    if (idx >= BATCH * NOUT) return;

    float mem = 0.f;
#pragma unroll
    for (int t = 0; t < NUM_STEPS; t++) {
        const float c   = g_cur2[(size_t)t * (BATCH * NOUT) + idx];
        const float rst = (mem > THRESH) ? THRESH : 0.f;
        mem = __fsub_rn(__fadd_rn(__fmul_rn(BETA, mem), c), rst);
        const float spk = (mem > THRESH) ? 1.f : 0.f;
        out[(size_t)t * (BATCH * NOUT) + idx] = spk;
        out[(size_t)NUM_STEPS * BATCH * NOUT + (size_t)t * (BATCH * NOUT) + idx] = mem;
    }
}

// ---------------------------------------------------------------------------
extern "C" void kernel_launch(void* const* d_in, const int* in_sizes, int n_in,
                              void* d_out, int out_size)
{
    const float* x  = (const float*)d_in[0];   // [25,4096,784]
    const float* W1 = (const float*)d_in[1];   // [1000,784]
    const float* b1 = (const float*)d_in[2];   // [1000]
    const float* W2 = (const float*)d_in[3];   // [10,1000]
    const float* b2 = (const float*)d_in[4];   // [10]
    float* out = (float*)d_out;

    xnorm_kernel<<<MTOT / 8, 256>>>(x);
    wnorm_kernel<<<1024 / 8, 256>>>(W1);

    dim3 g1((NHID + BN - 1) / BN, MTOT / BM);  // (8, 800)
    gemm1f_kernel<<<g1, 256>>>(x, W1, b1);

    flag_kernel<<<(BATCH * 32) / 8, 256>>>();

    fixup_kernel<<<BATCH, 256>>>(x, W1, b1);

    rec1_kernel<<<(BATCH * 32) / 8, 256>>>();

    gemm2_kernel<<<MTOT / 256, 256>>>(W2, b2);

    rec2_kernel<<<(BATCH * NOUT + 255) / 256, 256>>>(out);
}

// round 10
// speedup vs baseline: 6.4593x; 6.4593x over previous
#include <cuda_runtime.h>
#include <stdint.h>

// Problem constants
#define NUM_STEPS 25
#define BATCH     4096
#define NIN       784
#define NHID      1000
#define NOUT      10
#define MTOT      (NUM_STEPS * BATCH)   // 102400
#define BETA      0.95f
#define THRESH    1.0f

// Per-step cur1 uncertainty window: ~300x the measured RMS deviation between
// the fused FFMA chain and the reference's unfused chain (~3e-7). Missed-flip
// probability is negligible; flag rate stays ~1-2%.
#define DELTA 1e-4f

// Scratch (device globals; no runtime allocation allowed)
__device__ float    g_cur1[(size_t)MTOT * NHID];     // [t*B+b][h] approx; patched exact where flagged
__device__ uint32_t g_maskT[(size_t)32 * MTOT];      // spk1 bits, [word][row]
__device__ float    g_cur2[(size_t)MTOT * NOUT];     // [t*B+b][o]
__device__ uint32_t g_flag[BATCH * 32];              // chain-uncertain bitmask [b][chunk]

// ---------------------------------------------------------------------------
// Kernel 1: APPROX cur1 = X @ W1^T + b1 via FUSED FFMA chain (ascending k,
// 1 instr/MAC). Double-buffered 128x128x16 tile, register prefetch.
// ---------------------------------------------------------------------------
#define BM 128
#define BN 128
#define BK 16
#define NT (NIN / BK)     // 49 k-tiles
#define LDA (BM + 4)
#define LDB (BN + 4)

__global__ void __launch_bounds__(256, 2)
gemm1f_kernel(const float* __restrict__ X, const float* __restrict__ W1,
              const float* __restrict__ b1)
{
    __shared__ float As[2][BK * LDA];
    __shared__ float Bs[2][BK * LDB];

    const int tid = threadIdx.x;
    const int bm  = blockIdx.y * BM;
    const int bn  = blockIdx.x * BN;

    const int lr  = tid >> 2;
    const int lc4 = (tid & 3) * 4;

    const int tx   = tid & 15;
    const int ty   = tid >> 4;
    const int row0 = ty * 8;
    const int col0 = tx * 8;

    const float* Xp0 = X  + (size_t)(bm + lr) * NIN + lc4;
    const float* Xp1 = X  + (size_t)(bm + lr + 64) * NIN + lc4;
    const int    n0  = bn + lr;
    const int    n1  = bn + lr + 64;
    const float* Wp0 = W1 + (size_t)n0 * NIN + lc4;
    const float* Wp1 = W1 + (size_t)n1 * NIN + lc4;
    const bool   v0  = (n0 < NHID);
    const bool   v1  = (n1 < NHID);

    float acc[8][8];
#pragma unroll
    for (int i = 0; i < 8; i++)
#pragma unroll
        for (int j = 0; j < 8; j++) acc[i][j] = 0.f;

    float4 pa0, pa1, pb0, pb1;

    pa0 = *(const float4*)(Xp0);
    pa1 = *(const float4*)(Xp1);
    pb0 = v0 ? *(const float4*)(Wp0) : make_float4(0.f, 0.f, 0.f, 0.f);
    pb1 = v1 ? *(const float4*)(Wp1) : make_float4(0.f, 0.f, 0.f, 0.f);
    {
        float* as = As[0]; float* bs = Bs[0];
        as[(lc4 + 0) * LDA + lr]      = pa0.x;
        as[(lc4 + 1) * LDA + lr]      = pa0.y;
        as[(lc4 + 2) * LDA + lr]      = pa0.z;
        as[(lc4 + 3) * LDA + lr]      = pa0.w;
        as[(lc4 + 0) * LDA + lr + 64] = pa1.x;
        as[(lc4 + 1) * LDA + lr + 64] = pa1.y;
        as[(lc4 + 2) * LDA + lr + 64] = pa1.z;
        as[(lc4 + 3) * LDA + lr + 64] = pa1.w;
        bs[(lc4 + 0) * LDB + lr]      = pb0.x;
        bs[(lc4 + 1) * LDB + lr]      = pb0.y;
        bs[(lc4 + 2) * LDB + lr]      = pb0.z;
        bs[(lc4 + 3) * LDB + lr]      = pb0.w;
        bs[(lc4 + 0) * LDB + lr + 64] = pb1.x;
        bs[(lc4 + 1) * LDB + lr + 64] = pb1.y;
        bs[(lc4 + 2) * LDB + lr + 64] = pb1.z;
        bs[(lc4 + 3) * LDB + lr + 64] = pb1.w;
    }
    __syncthreads();

#pragma unroll 1
    for (int kt = 0; kt < NT; kt++) {
        const int cur = kt & 1;

        if (kt + 1 < NT) {
            const int koff = (kt + 1) * BK;
            pa0 = *(const float4*)(Xp0 + koff);
            pa1 = *(const float4*)(Xp1 + koff);
            pb0 = v0 ? *(const float4*)(Wp0 + koff) : make_float4(0.f, 0.f, 0.f, 0.f);
            pb1 = v1 ? *(const float4*)(Wp1 + koff) : make_float4(0.f, 0.f, 0.f, 0.f);
        }

        const float* as = As[cur];
        const float* bs = Bs[cur];
#pragma unroll
        for (int k = 0; k < BK; k++) {
            float a[8], b[8];
            *(float4*)(a)     = *(const float4*)&as[k * LDA + row0];
            *(float4*)(a + 4) = *(const float4*)&as[k * LDA + row0 + 4];
            *(float4*)(b)     = *(const float4*)&bs[k * LDB + col0];
            *(float4*)(b + 4) = *(const float4*)&bs[k * LDB + col0 + 4];
#pragma unroll
            for (int i = 0; i < 8; i++)
#pragma unroll
                for (int j = 0; j < 8; j++)
                    acc[i][j] = __fmaf_rn(a[i], b[j], acc[i][j]);
        }

        if (kt + 1 < NT) {
            const int nxt = (kt + 1) & 1;
            float* asn = As[nxt]; float* bsn = Bs[nxt];
            asn[(lc4 + 0) * LDA + lr]      = pa0.x;
            asn[(lc4 + 1) * LDA + lr]      = pa0.y;
            asn[(lc4 + 2) * LDA + lr]      = pa0.z;
            asn[(lc4 + 3) * LDA + lr]      = pa0.w;
            asn[(lc4 + 0) * LDA + lr + 64] = pa1.x;
            asn[(lc4 + 1) * LDA + lr + 64] = pa1.y;
            asn[(lc4 + 2) * LDA + lr + 64] = pa1.z;
            asn[(lc4 + 3) * LDA + lr + 64] = pa1.w;
            bsn[(lc4 + 0) * LDB + lr]      = pb0.x;
            bsn[(lc4 + 1) * LDB + lr]      = pb0.y;
            bsn[(lc4 + 2) * LDB + lr]      = pb0.z;
            bsn[(lc4 + 3) * LDB + lr]      = pb0.w;
            bsn[(lc4 + 0) * LDB + lr + 64] = pb1.x;
            bsn[(lc4 + 1) * LDB + lr + 64] = pb1.y;
            bsn[(lc4 + 2) * LDB + lr + 64] = pb1.z;
            bsn[(lc4 + 3) * LDB + lr + 64] = pb1.w;
            __syncthreads();
        }
    }

#pragma unroll
    for (int i = 0; i < 8; i++) {
        const int m = bm + row0 + i;
#pragma unroll
        for (int j = 0; j < 8; j++) {
            const int n = bn + col0 + j;
            if (n < NHID)
                g_cur1[(size_t)m * NHID + n] = __fadd_rn(acc[i][j], __ldg(&b1[n]));
        }
    }
}

// ---------------------------------------------------------------------------
// Flag kernel: recurrence over approx cur1 with propagated error radius
// e <- beta*e + DELTA + slop. Flags chains with any uncertain sign decision.
// ---------------------------------------------------------------------------
__global__ void __launch_bounds__(256)
flag_kernel()
{
    const int warp  = (blockIdx.x * blockDim.x + threadIdx.x) >> 5;
    const int lane  = threadIdx.x & 31;
    const int chunk = warp & 31;
    const int b     = warp >> 5;
    if (b >= BATCH) return;

    const int h = chunk * 32 + lane;
    const bool valid = (h < NHID);

    float mem = 0.f, e = 0.f;
    bool flg = false;
#pragma unroll
    for (int t = 0; t < NUM_STEPS; t++) {
        const float c = valid ? g_cur1[((size_t)t * BATCH + b) * NHID + h] : -1.f;
        const float rst = (mem > THRESH) ? THRESH : 0.f;
        mem = __fsub_rn(__fadd_rn(__fmul_rn(BETA, mem), c), rst);
        e = BETA * e + DELTA + 2e-7f * (fabsf(mem) + 2.f);
        flg = flg || (valid && fabsf(mem - THRESH) <= e);
    }
    const uint32_t w = __ballot_sync(0xffffffffu, flg);
    if (lane == 0) g_flag[b * 32 + chunk] = w;
}

// ---------------------------------------------------------------------------
// Fixup kernel v2 (coalesced): CTA per b. Stage the 25 X rows in smem
// (stride 785 -> conflict-free across lane=t). Each warp takes one flagged h;
// lanes 0..24 recompute the EXACT unfused ascending chain for (t, b, h).
// W1[k] is a broadcast load (1 sector), L1-resident across the warp's loop.
// ---------------------------------------------------------------------------
#define XLD 785   // odd stride -> lane banks 17*t mod 32, all distinct

__global__ void __launch_bounds__(256)
fixup_kernel(const float* __restrict__ X, const float* __restrict__ W1,
             const float* __restrict__ b1)
{
    extern __shared__ float xs[];                  // [25][XLD]
    __shared__ unsigned short list[1024];
    __shared__ int cnt;

    const int b   = blockIdx.x;
    const int tid = threadIdx.x;
    if (tid == 0) cnt = 0;
    __syncthreads();

    for (int h = tid; h < NHID; h += 256) {
        if ((g_flag[b * 32 + (h >> 5)] >> (h & 31)) & 1u) {
            const int idx = atomicAdd(&cnt, 1);
            list[idx] = (unsigned short)h;
        }
    }
    __syncthreads();

    const int nf = cnt;
    if (nf == 0) return;

    // stage X rows for this b (coalesced gmem reads)
    for (int i = tid; i < NUM_STEPS * NIN; i += 256) {
        const int t = i / NIN, k = i - t * NIN;
        xs[t * XLD + k] = X[((size_t)t * BATCH + b) * NIN + k];
    }
    __syncthreads();

    const int warpid = tid >> 5;
    const int lane   = tid & 31;

    for (int u = warpid; u < nf; u += 8) {
        const int h = (int)list[u];
        const float* wrow = W1 + (size_t)h * NIN;

        if (lane < NUM_STEPS) {
            const float* xr = xs + lane * XLD;
            float acc = 0.f;
#pragma unroll 8
            for (int k = 0; k < NIN; k++)
                acc = __fadd_rn(acc, __fmul_rn(xr[k], __ldg(wrow + k)));
            g_cur1[((size_t)lane * BATCH + b) * NHID + h] =
                __fadd_rn(acc, __ldg(&b1[h]));
        }
    }
}

// ---------------------------------------------------------------------------
// Kernel 2: layer-1 recurrence on patched cur1 -> spk1 transposed bitmask.
// ---------------------------------------------------------------------------
__global__ void __launch_bounds__(256)
rec1_kernel()
{
    const int warp  = (blockIdx.x * blockDim.x + threadIdx.x) >> 5;
    const int lane  = threadIdx.x & 31;
    const int chunk = warp & 31;
    const int b     = warp >> 5;
    if (b >= BATCH) return;

    const int h = chunk * 32 + lane;
    const bool valid = (h < NHID);

    float mem = 0.f;
#pragma unroll
    for (int t = 0; t < NUM_STEPS; t++) {
        const float c = valid ? g_cur1[((size_t)t * BATCH + b) * NHID + h] : -1.f;
        const float rst = (mem > THRESH) ? THRESH : 0.f;
        mem = __fsub_rn(__fadd_rn(__fmul_rn(BETA, mem), c), rst);
        const uint32_t w = __ballot_sync(0xffffffffu, mem > THRESH);
        if (lane == 0)
            g_maskT[(size_t)chunk * MTOT + (size_t)t * BATCH + b] = w;
    }
}

// ---------------------------------------------------------------------------
// Kernel 3: cur2 = spk1 @ W2^T + b2 (spk in {0,1} -> fma chain bit-identical
// to the unfused ascending chain).
// ---------------------------------------------------------------------------
#define W2LD 12

__global__ void __launch_bounds__(256)
gemm2_kernel(const float* __restrict__ W2, const float* __restrict__ b2)
{
    __shared__ float W2t[1000 * W2LD];
    for (int i = threadIdx.x; i < NOUT * NHID; i += 256) {
        const int o = i / NHID, h = i - o * NHID;
        W2t[h * W2LD + o] = W2[i];
    }
    __syncthreads();

    const int row = blockIdx.x * 256 + threadIdx.x;

    float acc[NOUT];
#pragma unroll
    for (int o = 0; o < NOUT; o++) acc[o] = 0.f;

#pragma unroll 1
    for (int wd = 0; wd < 32; wd++) {
        const uint32_t w = g_maskT[(size_t)wd * MTOT + row];
        const int nb = (wd < 31) ? 32 : (NHID - 31 * 32);
#pragma unroll 8
        for (int bit = 0; bit < nb; bit++) {
            const float f = (float)((w >> bit) & 1u);
            const int h = wd * 32 + bit;
            const float* wrow = &W2t[h * W2LD];
            float4 w0 = *(const float4*)(wrow);
            float4 w1 = *(const float4*)(wrow + 4);
            float2 w2v = *(const float2*)(wrow + 8);
            acc[0] = __fmaf_rn(f, w0.x, acc[0]);
            acc[1] = __fmaf_rn(f, w0.y, acc[1]);
            acc[2] = __fmaf_rn(f, w0.z, acc[2]);
            acc[3] = __fmaf_rn(f, w0.w, acc[3]);
            acc[4] = __fmaf_rn(f, w1.x, acc[4]);
            acc[5] = __fmaf_rn(f, w1.y, acc[5]);
            acc[6] = __fmaf_rn(f, w1.z, acc[6]);
            acc[7] = __fmaf_rn(f, w1.w, acc[7]);
            acc[8] = __fmaf_rn(f, w2v.x, acc[8]);
            acc[9] = __fmaf_rn(f, w2v.y, acc[9]);
        }
    }

    float* out = g_cur2 + (size_t)row * NOUT;
#pragma unroll
    for (int o = 0; o < NOUT; o++)
        out[o] = __fadd_rn(acc[o], __ldg(&b2[o]));
}

// ---------------------------------------------------------------------------
// Kernel 4: layer-2 recurrence + outputs [spk_rec | mem_rec].
// ---------------------------------------------------------------------------
__global__ void __launch_bounds__(256)
rec2_kernel(float* __restrict__ out)
{
    const int idx = blockIdx.x * blockDim.x + threadIdx.x;
    if (idx >= BATCH * NOUT) return;

    float mem = 0.f;
#pragma unroll
    for (int t = 0; t < NUM_STEPS; t++) {
        const float c   = g_cur2[(size_t)t * (BATCH * NOUT) + idx];
        const float rst = (mem > THRESH) ? THRESH : 0.f;
        mem = __fsub_rn(__fadd_rn(__fmul_rn(BETA, mem), c), rst);
        const float spk = (mem > THRESH) ? 1.f : 0.f;
        out[(size_t)t * (BATCH * NOUT) + idx] = spk;
        out[(size_t)NUM_STEPS * BATCH * NOUT + (size_t)t * (BATCH * NOUT) + idx] = mem;
    }
}

// ---------------------------------------------------------------------------
extern "C" void kernel_launch(void* const* d_in, const int* in_sizes, int n_in,
                              void* d_out, int out_size)
{
    const float* x  = (const float*)d_in[0];   // [25,4096,784]
    const float* W1 = (const float*)d_in[1];   // [1000,784]
    const float* b1 = (const float*)d_in[2];   // [1000]
    const float* W2 = (const float*)d_in[3];   // [10,1000]
    const float* b2 = (const float*)d_in[4];   // [10]
    float* out = (float*)d_out;

    const int xs_bytes = NUM_STEPS * XLD * (int)sizeof(float);   // 78.5 KB
    cudaFuncSetAttribute(fixup_kernel,
                         cudaFuncAttributeMaxDynamicSharedMemorySize, xs_bytes);

    dim3 g1((NHID + BN - 1) / BN, MTOT / BM);  // (8, 800)
    gemm1f_kernel<<<g1, 256>>>(x, W1, b1);

    flag_kernel<<<(BATCH * 32) / 8, 256>>>();

    fixup_kernel<<<BATCH, 256, xs_bytes>>>(x, W1, b1);

    rec1_kernel<<<(BATCH * 32) / 8, 256>>>();

    gemm2_kernel<<<MTOT / 256, 256>>>(W2, b2);

    rec2_kernel<<<(BATCH * NOUT + 255) / 256, 256>>>(out);
}

// round 12
// speedup vs baseline: 11.5181x; 1.7832x over previous
#include <cuda_runtime.h>
#include <cuda_bf16.h>
#include <stdint.h>

// Problem constants
#define NUM_STEPS 25
#define BATCH     4096
#define NIN       784
#define NHID      1000
#define NOUT      10
#define MTOT      (NUM_STEPS * BATCH)   // 102400
#define BETA      0.95f
#define THRESH    1.0f

// Flag window per step: covers bf16 hi/lo split residual + dropped lo*lo term
// + HMMA accumulation-order deviation (all <= ~5e-5 worst case), with margin.
#define DELTA 1e-4f

// Scratch (device globals; no runtime allocation allowed)
__device__ float          g_cur1[(size_t)MTOT * NHID];
__device__ uint32_t       g_maskT[(size_t)32 * MTOT];
__device__ float          g_cur2[(size_t)MTOT * NOUT];
__device__ uint32_t       g_flag[BATCH * 32];
__device__ __nv_bfloat16  g_xh[(size_t)MTOT * NIN];
__device__ __nv_bfloat16  g_xl[(size_t)MTOT * NIN];
__device__ __nv_bfloat16  g_wh[(size_t)1024 * NIN];
__device__ __nv_bfloat16  g_wl[(size_t)1024 * NIN];

static __device__ __forceinline__ uint32_t smem_u32(const void* p) {
    uint32_t a;
    asm("{ .reg .u64 t; cvta.to.shared.u64 t, %1; cvt.u32.u64 %0, t; }"
        : "=r"(a) : "l"(p));
    return a;
}

#define LDMX4(r0, r1, r2, r3, a) \
    asm volatile("ldmatrix.sync.aligned.m8n8.x4.shared.b16 {%0,%1,%2,%3}, [%4];" \
                 : "=r"(r0), "=r"(r1), "=r"(r2), "=r"(r3) : "r"(a))

#define MMA_BF16(c, a, b) \
    asm volatile("mma.sync.aligned.m16n8k16.row.col.f32.bf16.bf16.f32 " \
                 "{%0,%1,%2,%3}, {%4,%5,%6,%7}, {%8,%9}, {%0,%1,%2,%3};" \
                 : "+f"((c)[0]), "+f"((c)[1]), "+f"((c)[2]), "+f"((c)[3]) \
                 : "r"((a)[0]), "r"((a)[1]), "r"((a)[2]), "r"((a)[3]), \
                   "r"((b)[0]), "r"((b)[1]))

// ---------------------------------------------------------------------------
// Split kernels: x = xh + xl (bf16 hi + bf16 residual).
// ---------------------------------------------------------------------------
__global__ void __launch_bounds__(256)
splitx_kernel(const float* __restrict__ X)
{
    const size_t m = blockIdx.x;
    for (int k = threadIdx.x; k < NIN; k += 256) {
        const float v = X[m * NIN + k];
        const __nv_bfloat16 h = __float2bfloat16(v);
        g_xh[m * NIN + k] = h;
        g_xl[m * NIN + k] = __float2bfloat16(v - __bfloat162float(h));
    }
}

__global__ void __launch_bounds__(256)
splitw_kernel(const float* __restrict__ W1)
{
    const size_t h = blockIdx.x;
    for (int k = threadIdx.x; k < NIN; k += 256) {
        const float v = (h < NHID) ? W1[h * NIN + k] : 0.f;
        const __nv_bfloat16 hh = __float2bfloat16(v);
        g_wh[h * NIN + k] = hh;
        g_wl[h * NIN + k] = __float2bfloat16(v - __bfloat162float(hh));
    }
}

// ---------------------------------------------------------------------------
// gemm1 on HMMA: cur1 ~= Xh@Wh^T + Xh@Wl^T + Xl@Wh^T + b1.
// CTA tile 128(M)x128(N), 8 warps (2x4), warp tile 64x32, K in 49 steps of 16.
// smem: per stage 4 tiles (Ah, Al, Bh, Bl), each 128 rows x 48B (16 bf16 used,
// padded for conflict-free ldmatrix). Double-buffered, register prefetch.
// ---------------------------------------------------------------------------
#define TILE_BYTES 6144        // 128 * 48
#define STAGE_BYTES 24576      // 4 tiles
#define NKS 49

__global__ void __launch_bounds__(256)
gemm1t_kernel(const float* __restrict__ b1)
{
    __shared__ __align__(16) char smem[2][STAGE_BYTES];

    const int tid    = threadIdx.x;
    const int wid    = tid >> 5;
    const int lane   = tid & 31;
    const int bm     = blockIdx.y * 128;
    const int bn     = blockIdx.x * 128;
    const int warp_m = (wid >> 2) * 64;
    const int warp_n = (wid & 3) * 32;

    // loader mapping: row = tid>>1 (0..127), 16B chunk = tid&1
    const int lrow = tid >> 1;
    const int lc   = tid & 1;
    const __nv_bfloat16* gxh = g_xh + (size_t)(bm + lrow) * NIN + lc * 8;
    const __nv_bfloat16* gxl = g_xl + (size_t)(bm + lrow) * NIN + lc * 8;
    const __nv_bfloat16* gwh = g_wh + (size_t)(bn + lrow) * NIN + lc * 8;
    const __nv_bfloat16* gwl = g_wl + (size_t)(bn + lrow) * NIN + lc * 8;
    const int soff = lrow * 48 + lc * 16;

    const uint32_t sb = smem_u32(smem);
    // ldmatrix lane offsets
    const uint32_t aoff = (uint32_t)((warp_m + (lane & 15)) * 48 + (lane >> 4) * 16);
    const uint32_t boff0 = (uint32_t)((warp_n + ((lane >> 4) << 3) + (lane & 7)) * 48
                                      + ((lane >> 3) & 1) * 16);
    const uint32_t boff1 = boff0 + 16 * 48;

    float acc[4][4][4];
#pragma unroll
    for (int i = 0; i < 4; i++)
#pragma unroll
        for (int j = 0; j < 4; j++)
#pragma unroll
            for (int r = 0; r < 4; r++) acc[i][j][r] = 0.f;

    uint4 p0, p1, p2, p3;
    // prologue: k-step 0 -> stage 0
    p0 = *(const uint4*)(gxh);
    p1 = *(const uint4*)(gxl);
    p2 = *(const uint4*)(gwh);
    p3 = *(const uint4*)(gwl);
    {
        char* s = smem[0] + soff;
        *(uint4*)(s)                  = p0;
        *(uint4*)(s + TILE_BYTES)     = p1;
        *(uint4*)(s + 2 * TILE_BYTES) = p2;
        *(uint4*)(s + 3 * TILE_BYTES) = p3;
    }
    __syncthreads();

#pragma unroll 1
    for (int kt = 0; kt < NKS; kt++) {
        const int cur = kt & 1;

        if (kt + 1 < NKS) {
            const int ko = (kt + 1) * 16;
            p0 = *(const uint4*)(gxh + ko);
            p1 = *(const uint4*)(gxl + ko);
            p2 = *(const uint4*)(gwh + ko);
            p3 = *(const uint4*)(gwl + ko);
        }

        const uint32_t st = sb + (uint32_t)cur * STAGE_BYTES;

        // B fragments: bh/bl for 4 n8-tiles
        uint32_t bh[8], bl[8];
        LDMX4(bh[0], bh[1], bh[2], bh[3], st + 2 * TILE_BYTES + boff0);
        LDMX4(bh[4], bh[5], bh[6], bh[7], st + 2 * TILE_BYTES + boff1);
        LDMX4(bl[0], bl[1], bl[2], bl[3], st + 3 * TILE_BYTES + boff0);
        LDMX4(bl[4], bl[5], bl[6], bl[7], st + 3 * TILE_BYTES + boff1);

#pragma unroll
        for (int mi = 0; mi < 4; mi++) {
            uint32_t ah[4], al[4];
            LDMX4(ah[0], ah[1], ah[2], ah[3], st + aoff + mi * (16 * 48));
            LDMX4(al[0], al[1], al[2], al[3], st + TILE_BYTES + aoff + mi * (16 * 48));
#pragma unroll
            for (int nj = 0; nj < 4; nj++) {
                uint32_t bhf[2] = {bh[nj * 2], bh[nj * 2 + 1]};
                uint32_t blf[2] = {bl[nj * 2], bl[nj * 2 + 1]};
                MMA_BF16(acc[mi][nj], ah, bhf);   // hh
                MMA_BF16(acc[mi][nj], ah, blf);   // hl
                MMA_BF16(acc[mi][nj], al, bhf);   // lh
            }
        }

        if (kt + 1 < NKS) {
            char* s = smem[(kt + 1) & 1] + soff;
            *(uint4*)(s)                  = p0;
            *(uint4*)(s + TILE_BYTES)     = p1;
            *(uint4*)(s + 2 * TILE_BYTES) = p2;
            *(uint4*)(s + 3 * TILE_BYTES) = p3;
            __syncthreads();
        }
    }

    // epilogue: d-frag lane mapping: rows {l/4, l/4+8}, cols {2(l%4), +1}
    const int m0 = bm + warp_m + (lane >> 2);
    const int n0 = bn + warp_n + (lane & 3) * 2;
#pragma unroll
    for (int mi = 0; mi < 4; mi++) {
#pragma unroll
        for (int nj = 0; nj < 4; nj++) {
            const int n = n0 + nj * 8;
            if (n < NHID - 1) {
                const float bx = __ldg(&b1[n]);
                const float by = __ldg(&b1[n + 1]);
                const int mA = m0 + mi * 16;
                float2 v0, v1;
                v0.x = __fadd_rn(acc[mi][nj][0], bx);
                v0.y = __fadd_rn(acc[mi][nj][1], by);
                v1.x = __fadd_rn(acc[mi][nj][2], bx);
                v1.y = __fadd_rn(acc[mi][nj][3], by);
                *(float2*)&g_cur1[(size_t)mA * NHID + n] = v0;
                *(float2*)&g_cur1[(size_t)(mA + 8) * NHID + n] = v1;
            }
        }
    }
}

// ---------------------------------------------------------------------------
// Flag kernel: recurrence with error radius e <- beta*e + DELTA + slop.
// ---------------------------------------------------------------------------
__global__ void __launch_bounds__(256)
flag_kernel()
{
    const int warp  = (blockIdx.x * blockDim.x + threadIdx.x) >> 5;
    const int lane  = threadIdx.x & 31;
    const int chunk = warp & 31;
    const int b     = warp >> 5;
    if (b >= BATCH) return;

    const int h = chunk * 32 + lane;
    const bool valid = (h < NHID);

    float mem = 0.f, e = 0.f;
    bool flg = false;
#pragma unroll
    for (int t = 0; t < NUM_STEPS; t++) {
        const float c = valid ? g_cur1[((size_t)t * BATCH + b) * NHID + h] : -1.f;
        const float rst = (mem > THRESH) ? THRESH : 0.f;
        mem = __fsub_rn(__fadd_rn(__fmul_rn(BETA, mem), c), rst);
        e = BETA * e + DELTA + 2e-7f * (fabsf(mem) + 2.f);
        flg = flg || (valid && fabsf(mem - THRESH) <= e);
    }
    const uint32_t w = __ballot_sync(0xffffffffu, flg);
    if (lane == 0) g_flag[b * 32 + chunk] = w;
}

// ---------------------------------------------------------------------------
// Fixup: recompute EXACT unfused ascending chain for flagged (b,h).
// ---------------------------------------------------------------------------
#define XLD 785

__global__ void __launch_bounds__(256)
fixup_kernel(const float* __restrict__ X, const float* __restrict__ W1,
             const float* __restrict__ b1)
{
    extern __shared__ float xs[];
    __shared__ unsigned short list[1024];
    __shared__ int cnt;

    const int b   = blockIdx.x;
    const int tid = threadIdx.x;
    if (tid == 0) cnt = 0;
    __syncthreads();

    for (int h = tid; h < NHID; h += 256) {
        if ((g_flag[b * 32 + (h >> 5)] >> (h & 31)) & 1u) {
            const int idx = atomicAdd(&cnt, 1);
            list[idx] = (unsigned short)h;
        }
    }
    __syncthreads();

    const int nf = cnt;
    if (nf == 0) return;

    for (int i = tid; i < NUM_STEPS * NIN; i += 256) {
        const int t = i / NIN, k = i - t * NIN;
        xs[t * XLD + k] = X[((size_t)t * BATCH + b) * NIN + k];
    }
    __syncthreads();

    const int warpid = tid >> 5;
    const int lane   = tid & 31;

    for (int u = warpid; u < nf; u += 8) {
        const int h = (int)list[u];
        const float* wrow = W1 + (size_t)h * NIN;

        if (lane < NUM_STEPS) {
            const float* xr = xs + lane * XLD;
            float acc = 0.f;
#pragma unroll 8
            for (int k = 0; k < NIN; k++)
                acc = __fadd_rn(acc, __fmul_rn(xr[k], __ldg(wrow + k)));
            g_cur1[((size_t)lane * BATCH + b) * NHID + h] =
                __fadd_rn(acc, __ldg(&b1[h]));
        }
    }
}

// ---------------------------------------------------------------------------
// rec1: layer-1 recurrence on patched cur1 -> spk1 transposed bitmask.
// ---------------------------------------------------------------------------
__global__ void __launch_bounds__(256)
rec1_kernel()
{
    const int warp  = (blockIdx.x * blockDim.x + threadIdx.x) >> 5;
    const int lane  = threadIdx.x & 31;
    const int chunk = warp & 31;
    const int b     = warp >> 5;
    if (b >= BATCH) return;

    const int h = chunk * 32 + lane;
    const bool valid = (h < NHID);

    float mem = 0.f;
#pragma unroll
    for (int t = 0; t < NUM_STEPS; t++) {
        const float c = valid ? g_cur1[((size_t)t * BATCH + b) * NHID + h] : -1.f;
        const float rst = (mem > THRESH) ? THRESH : 0.f;
        mem = __fsub_rn(__fadd_rn(__fmul_rn(BETA, mem), c), rst);
        const uint32_t w = __ballot_sync(0xffffffffu, mem > THRESH);
        if (lane == 0)
            g_maskT[(size_t)chunk * MTOT + (size_t)t * BATCH + b] = w;
    }
}

// ---------------------------------------------------------------------------
// gemm2: cur2 = spk1 @ W2^T + b2 (bit-identical to unfused ascending chain).
// ---------------------------------------------------------------------------
#define W2LD 12

__global__ void __launch_bounds__(256)
gemm2_kernel(const float* __restrict__ W2, const float* __restrict__ b2)
{
    __shared__ float W2t[1000 * W2LD];
    for (int i = threadIdx.x; i < NOUT * NHID; i += 256) {
        const int o = i / NHID, h = i - o * NHID;
        W2t[h * W2LD + o] = W2[i];
    }
    __syncthreads();

    const int row = blockIdx.x * 256 + threadIdx.x;

    float acc[NOUT];
#pragma unroll
    for (int o = 0; o < NOUT; o++) acc[o] = 0.f;

#pragma unroll 1
    for (int wd = 0; wd < 32; wd++) {
        const uint32_t w = g_maskT[(size_t)wd * MTOT + row];
        const int nb = (wd < 31) ? 32 : (NHID - 31 * 32);
#pragma unroll 8
        for (int bit = 0; bit < nb; bit++) {
            const float f = (float)((w >> bit) & 1u);
            const int h = wd * 32 + bit;
            const float* wrow = &W2t[h * W2LD];
            float4 w0 = *(const float4*)(wrow);
            float4 w1 = *(const float4*)(wrow + 4);
            float2 w2v = *(const float2*)(wrow + 8);
            acc[0] = __fmaf_rn(f, w0.x, acc[0]);
            acc[1] = __fmaf_rn(f, w0.y, acc[1]);
            acc[2] = __fmaf_rn(f, w0.z, acc[2]);
            acc[3] = __fmaf_rn(f, w0.w, acc[3]);
            acc[4] = __fmaf_rn(f, w1.x, acc[4]);
            acc[5] = __fmaf_rn(f, w1.y, acc[5]);
            acc[6] = __fmaf_rn(f, w1.z, acc[6]);
            acc[7] = __fmaf_rn(f, w1.w, acc[7]);
            acc[8] = __fmaf_rn(f, w2v.x, acc[8]);
            acc[9] = __fmaf_rn(f, w2v.y, acc[9]);
        }
    }

    float* out = g_cur2 + (size_t)row * NOUT;
#pragma unroll
    for (int o = 0; o < NOUT; o++)
        out[o] = __fadd_rn(acc[o], __ldg(&b2[o]));
}

// ---------------------------------------------------------------------------
// rec2: layer-2 recurrence + outputs [spk_rec | mem_rec].
// ---------------------------------------------------------------------------
__global__ void __launch_bounds__(256)
rec2_kernel(float* __restrict__ out)
{
    const int idx = blockIdx.x * blockDim.x + threadIdx.x;
    if (idx >= BATCH * NOUT) return;

    float mem = 0.f;
#pragma unroll
    for (int t = 0; t < NUM_STEPS; t++) {
        const float c   = g_cur2[(size_t)t * (BATCH * NOUT) + idx];
        const float rst = (mem > THRESH) ? THRESH : 0.f;
        mem = __fsub_rn(__fadd_rn(__fmul_rn(BETA, mem), c), rst);
        const float spk = (mem > THRESH) ? 1.f : 0.f;
        out[(size_t)t * (BATCH * NOUT) + idx] = spk;
        out[(size_t)NUM_STEPS * BATCH * NOUT + (size_t)t * (BATCH * NOUT) + idx] = mem;
    }
}

// ---------------------------------------------------------------------------
extern "C" void kernel_launch(void* const* d_in, const int* in_sizes, int n_in,
                              void* d_out, int out_size)
{
    const float* x  = (const float*)d_in[0];
    const float* W1 = (const float*)d_in[1];
    const float* b1 = (const float*)d_in[2];
    const float* W2 = (const float*)d_in[3];
    const float* b2 = (const float*)d_in[4];
    float* out = (float*)d_out;

    const int xs_bytes = NUM_STEPS * XLD * (int)sizeof(float);
    cudaFuncSetAttribute(fixup_kernel,
                         cudaFuncAttributeMaxDynamicSharedMemorySize, xs_bytes);

    splitx_kernel<<<MTOT, 256>>>(x);
    splitw_kernel<<<1024, 256>>>(W1);

    dim3 g1(8, MTOT / 128);   // n-blocks x m-blocks
    gemm1t_kernel<<<g1, 256>>>(b1);

    flag_kernel<<<(BATCH * 32) / 8, 256>>>();

    fixup_kernel<<<BATCH, 256, xs_bytes>>>(x, W1, b1);

    rec1_kernel<<<(BATCH * 32) / 8, 256>>>();

    gemm2_kernel<<<MTOT / 256, 256>>>(W2, b2);

    rec2_kernel<<<(BATCH * NOUT + 255) / 256, 256>>>(out);
}

// round 13
// speedup vs baseline: 13.0877x; 1.1363x over previous
#include <cuda_runtime.h>
#include <cuda_fp16.h>
#include <stdint.h>

// Problem constants
#define NUM_STEPS 25
#define BATCH     4096
#define NIN       784
#define NHID      1000
#define NOUT      10
#define MTOT      (NUM_STEPS * BATCH)   // 102400
#define BETA      0.95f
#define THRESH    1.0f

// Flag window per step: fp16 hi/lo split -> dropped lo*lo ~2e-7, subnormal
// wl representation <=1.2e-5 worst, accumulation-order ~1e-6 RMS. 4x margin.
#define DELTA 5e-5f

// Scratch (device globals; no runtime allocation allowed)
__device__ float     g_cur1[(size_t)MTOT * NHID];
__device__ uint32_t  g_maskT[(size_t)32 * MTOT];    // spk1 bits, [word][t*B+b]
__device__ float     g_cur2[(size_t)MTOT * NOUT];
__device__ uint32_t  g_flag[BATCH * 32];
__device__ __half    g_xh[(size_t)MTOT * NIN];
__device__ __half    g_xl[(size_t)MTOT * NIN];
__device__ __half    g_wh[(size_t)1024 * NIN];
__device__ __half    g_wl[(size_t)1024 * NIN];

static __device__ __forceinline__ uint32_t smem_u32(const void* p) {
    uint32_t a;
    asm("{ .reg .u64 t; cvta.to.shared.u64 t, %1; cvt.u32.u64 %0, t; }"
        : "=r"(a) : "l"(p));
    return a;
}

#define LDMX4(r0, r1, r2, r3, a) \
    asm volatile("ldmatrix.sync.aligned.m8n8.x4.shared.b16 {%0,%1,%2,%3}, [%4];" \
                 : "=r"(r0), "=r"(r1), "=r"(r2), "=r"(r3) : "r"(a))

#define MMA_F16(c, a, b) \
    asm volatile("mma.sync.aligned.m16n8k16.row.col.f32.f16.f16.f32 " \
                 "{%0,%1,%2,%3}, {%4,%5,%6,%7}, {%8,%9}, {%0,%1,%2,%3};" \
                 : "+f"((c)[0]), "+f"((c)[1]), "+f"((c)[2]), "+f"((c)[3]) \
                 : "r"((a)[0]), "r"((a)[1]), "r"((a)[2]), "r"((a)[3]), \
                   "r"((b)[0]), "r"((b)[1]))

// ---------------------------------------------------------------------------
// Split kernels: v = vh + vl (fp16 hi + fp16 residual).
// ---------------------------------------------------------------------------
__global__ void __launch_bounds__(256)
splitx_kernel(const float* __restrict__ X)
{
    const size_t m = blockIdx.x;
    for (int k = threadIdx.x; k < NIN; k += 256) {
        const float v = X[m * NIN + k];
        const __half h = __float2half_rn(v);
        g_xh[m * NIN + k] = h;
        g_xl[m * NIN + k] = __float2half_rn(v - __half2float(h));
    }
}

__global__ void __launch_bounds__(256)
splitw_kernel(const float* __restrict__ W1)
{
    const size_t h = blockIdx.x;
    for (int k = threadIdx.x; k < NIN; k += 256) {
        const float v = (h < NHID) ? W1[h * NIN + k] : 0.f;
        const __half hh = __float2half_rn(v);
        g_wh[h * NIN + k] = hh;
        g_wl[h * NIN + k] = __float2half_rn(v - __half2float(hh));
    }
}

// ---------------------------------------------------------------------------
// gemm1 on HMMA fp16: cur1 ~= Xh@Wh^T + Xh@Wl^T + Xl@Wh^T + b1.
// CTA tile 128x128, 8 warps (2x4), warp tile 64x32, K in 49 steps of 16.
// Per stage 4 tiles (Ah, Al, Bh, Bl), 128 rows x 48B. Double-buffered.
// ---------------------------------------------------------------------------
#define TILE_BYTES 6144        // 128 * 48
#define STAGE_BYTES 24576
#define NKS 49

__global__ void __launch_bounds__(256)
gemm1t_kernel(const float* __restrict__ b1)
{
    __shared__ __align__(16) char smem[2][STAGE_BYTES];

    const int tid    = threadIdx.x;
    const int wid    = tid >> 5;
    const int lane   = tid & 31;
    const int bm     = blockIdx.y * 128;
    const int bn     = blockIdx.x * 128;
    const int warp_m = (wid >> 2) * 64;
    const int warp_n = (wid & 3) * 32;

    const int lrow = tid >> 1;
    const int lc   = tid & 1;
    const __half* gxh = g_xh + (size_t)(bm + lrow) * NIN + lc * 8;
    const __half* gxl = g_xl + (size_t)(bm + lrow) * NIN + lc * 8;
    const __half* gwh = g_wh + (size_t)(bn + lrow) * NIN + lc * 8;
    const __half* gwl = g_wl + (size_t)(bn + lrow) * NIN + lc * 8;
    const int soff = lrow * 48 + lc * 16;

    const uint32_t sb = smem_u32(smem);
    const uint32_t aoff = (uint32_t)((warp_m + (lane & 15)) * 48 + (lane >> 4) * 16);
    const uint32_t boff0 = (uint32_t)((warp_n + ((lane >> 4) << 3) + (lane & 7)) * 48
                                      + ((lane >> 3) & 1) * 16);
    const uint32_t boff1 = boff0 + 16 * 48;

    float acc[4][4][4];
#pragma unroll
    for (int i = 0; i < 4; i++)
#pragma unroll
        for (int j = 0; j < 4; j++)
#pragma unroll
            for (int r = 0; r < 4; r++) acc[i][j][r] = 0.f;

    uint4 p0, p1, p2, p3;
    p0 = *(const uint4*)(gxh);
    p1 = *(const uint4*)(gxl);
    p2 = *(const uint4*)(gwh);
    p3 = *(const uint4*)(gwl);
    {
        char* s = smem[0] + soff;
        *(uint4*)(s)                  = p0;
        *(uint4*)(s + TILE_BYTES)     = p1;
        *(uint4*)(s + 2 * TILE_BYTES) = p2;
        *(uint4*)(s + 3 * TILE_BYTES) = p3;
    }
    __syncthreads();

#pragma unroll 1
    for (int kt = 0; kt < NKS; kt++) {
        const int cur = kt & 1;

        if (kt + 1 < NKS) {
            const int ko = (kt + 1) * 16;
            p0 = *(const uint4*)(gxh + ko);
            p1 = *(const uint4*)(gxl + ko);
            p2 = *(const uint4*)(gwh + ko);
            p3 = *(const uint4*)(gwl + ko);
        }

        const uint32_t st = sb + (uint32_t)cur * STAGE_BYTES;

        uint32_t bh[8], bl[8];
        LDMX4(bh[0], bh[1], bh[2], bh[3], st + 2 * TILE_BYTES + boff0);
        LDMX4(bh[4], bh[5], bh[6], bh[7], st + 2 * TILE_BYTES + boff1);
        LDMX4(bl[0], bl[1], bl[2], bl[3], st + 3 * TILE_BYTES + boff0);
        LDMX4(bl[4], bl[5], bl[6], bl[7], st + 3 * TILE_BYTES + boff1);

#pragma unroll
        for (int mi = 0; mi < 4; mi++) {
            uint32_t ah[4], al[4];
            LDMX4(ah[0], ah[1], ah[2], ah[3], st + aoff + mi * (16 * 48));
            LDMX4(al[0], al[1], al[2], al[3], st + TILE_BYTES + aoff + mi * (16 * 48));
#pragma unroll
            for (int nj = 0; nj < 4; nj++) {
                uint32_t bhf[2] = {bh[nj * 2], bh[nj * 2 + 1]};
                uint32_t blf[2] = {bl[nj * 2], bl[nj * 2 + 1]};
                MMA_F16(acc[mi][nj], ah, bhf);   // hh
                MMA_F16(acc[mi][nj], ah, blf);   // hl
                MMA_F16(acc[mi][nj], al, bhf);   // lh
            }
        }

        if (kt + 1 < NKS) {
            char* s = smem[(kt + 1) & 1] + soff;
            *(uint4*)(s)                  = p0;
            *(uint4*)(s + TILE_BYTES)     = p1;
            *(uint4*)(s + 2 * TILE_BYTES) = p2;
            *(uint4*)(s + 3 * TILE_BYTES) = p3;
            __syncthreads();
        }
    }

    const int m0 = bm + warp_m + (lane >> 2);
    const int n0 = bn + warp_n + (lane & 3) * 2;
#pragma unroll
    for (int mi = 0; mi < 4; mi++) {
#pragma unroll
        for (int nj = 0; nj < 4; nj++) {
            const int n = n0 + nj * 8;
            if (n < NHID - 1) {
                const float bx = __ldg(&b1[n]);
                const float by = __ldg(&b1[n + 1]);
                const int mA = m0 + mi * 16;
                float2 v0, v1;
                v0.x = __fadd_rn(acc[mi][nj][0], bx);
                v0.y = __fadd_rn(acc[mi][nj][1], by);
                v1.x = __fadd_rn(acc[mi][nj][2], bx);
                v1.y = __fadd_rn(acc[mi][nj][3], by);
                *(float2*)&g_cur1[(size_t)mA * NHID + n] = v0;
                *(float2*)&g_cur1[(size_t)(mA + 8) * NHID + n] = v1;
            }
        }
    }
}

// ---------------------------------------------------------------------------
// flagrec: recurrence on approx cur1 with error radius; writes PROVISIONAL
// spike mask (certified correct for unflagged chains) + per-chain flag bits.
// ---------------------------------------------------------------------------
__global__ void __launch_bounds__(256)
flagrec_kernel()
{
    const int warp  = (blockIdx.x * blockDim.x + threadIdx.x) >> 5;
    const int lane  = threadIdx.x & 31;
    const int chunk = warp & 31;
    const int b     = warp >> 5;
    if (b >= BATCH) return;

    const int h = chunk * 32 + lane;
    const bool valid = (h < NHID);

    float mem = 0.f, e = 0.f;
    bool flg = false;
#pragma unroll
    for (int t = 0; t < NUM_STEPS; t++) {
        const float c = valid ? g_cur1[((size_t)t * BATCH + b) * NHID + h] : -1.f;
        const float rst = (mem > THRESH) ? THRESH : 0.f;
        mem = __fsub_rn(__fadd_rn(__fmul_rn(BETA, mem), c), rst);
        e = BETA * e + DELTA + 2e-7f * (fabsf(mem) + 2.f);
        flg = flg || (valid && fabsf(mem - THRESH) <= e);
        const uint32_t w = __ballot_sync(0xffffffffu, mem > THRESH);
        if (lane == 0)
            g_maskT[(size_t)chunk * MTOT + (size_t)t * BATCH + b] = w;
    }
    const uint32_t f = __ballot_sync(0xffffffffu, flg);
    if (lane == 0) g_flag[b * 32 + chunk] = f;
}

// ---------------------------------------------------------------------------
// Fixup: for flagged (b,h), recompute EXACT unfused ascending chain and
// patch the mask bits directly (atomicOr/atomicAnd). CTA per b; lane = t.
// ---------------------------------------------------------------------------
#define XLD 785

__global__ void __launch_bounds__(256)
fixup_kernel(const float* __restrict__ X, const float* __restrict__ W1,
             const float* __restrict__ b1)
{
    extern __shared__ float xs[];
    __shared__ unsigned short list[1024];
    __shared__ int cnt;

    const int b   = blockIdx.x;
    const int tid = threadIdx.x;
    if (tid == 0) cnt = 0;
    __syncthreads();

    for (int h = tid; h < NHID; h += 256) {
        if ((g_flag[b * 32 + (h >> 5)] >> (h & 31)) & 1u) {
            const int idx = atomicAdd(&cnt, 1);
            list[idx] = (unsigned short)h;
        }
    }
    __syncthreads();

    const int nf = cnt;
    if (nf == 0) return;

    for (int i = tid; i < NUM_STEPS * NIN; i += 256) {
        const int t = i / NIN, k = i - t * NIN;
        xs[t * XLD + k] = X[((size_t)t * BATCH + b) * NIN + k];
    }
    __syncthreads();

    const int warpid = tid >> 5;
    const int lane   = tid & 31;

    for (int u = warpid; u < nf; u += 8) {
        const int h = (int)list[u];
        const float* wrow = W1 + (size_t)h * NIN;

        // lane t computes exact cur1(t, b, h): unfused ascending chain
        float dotv = 0.f;
        if (lane < NUM_STEPS) {
            const float* xr = xs + lane * XLD;
            float acc = 0.f;
#pragma unroll 8
            for (int k = 0; k < NIN; k++)
                acc = __fadd_rn(acc, __fmul_rn(xr[k], __ldg(wrow + k)));
            dotv = __fadd_rn(acc, __ldg(&b1[h]));
        }

        // exact recurrence across t (broadcast dots through the warp)
        float mem = 0.f;
        uint32_t myspk = 0;
#pragma unroll
        for (int t = 0; t < NUM_STEPS; t++) {
            const float c = __shfl_sync(0xffffffffu, dotv, t);
            const float rst = (mem > THRESH) ? THRESH : 0.f;
            mem = __fsub_rn(__fadd_rn(__fmul_rn(BETA, mem), c), rst);
            if (lane == t) myspk = (mem > THRESH) ? 1u : 0u;
        }

        if (lane < NUM_STEPS) {
            uint32_t* wp = &g_maskT[(size_t)(h >> 5) * MTOT +
                                    (size_t)lane * BATCH + b];
            const uint32_t bit = 1u << (h & 31);
            if (myspk) atomicOr(wp, bit);
            else       atomicAnd(wp, ~bit);
        }
    }
}

// ---------------------------------------------------------------------------
// gemm2: cur2 = spk1 @ W2^T + b2 (bit-identical to unfused ascending chain).
// ---------------------------------------------------------------------------
#define W2LD 12

__global__ void __launch_bounds__(256)
gemm2_kernel(const float* __restrict__ W2, const float* __restrict__ b2)
{
    __shared__ float W2t[1000 * W2LD];
    for (int i = threadIdx.x; i < NOUT * NHID; i += 256) {
        const int o = i / NHID, h = i - o * NHID;
        W2t[h * W2LD + o] = W2[i];
    }
    __syncthreads();

    const int row = blockIdx.x * 256 + threadIdx.x;

    float acc[NOUT];
#pragma unroll
    for (int o = 0; o < NOUT; o++) acc[o] = 0.f;

#pragma unroll 1
    for (int wd = 0; wd < 32; wd++) {
        const uint32_t w = g_maskT[(size_t)wd * MTOT + row];
        const int nb = (wd < 31) ? 32 : (NHID - 31 * 32);
#pragma unroll 8
        for (int bit = 0; bit < nb; bit++) {
            const float f = (float)((w >> bit) & 1u);
            const int h = wd * 32 + bit;
            const float* wrow = &W2t[h * W2LD];
            float4 w0 = *(const float4*)(wrow);
            float4 w1 = *(const float4*)(wrow + 4);
            float2 w2v = *(const float2*)(wrow + 8);
            acc[0] = __fmaf_rn(f, w0.x, acc[0]);
            acc[1] = __fmaf_rn(f, w0.y, acc[1]);
            acc[2] = __fmaf_rn(f, w0.z, acc[2]);
            acc[3] = __fmaf_rn(f, w0.w, acc[3]);
            acc[4] = __fmaf_rn(f, w1.x, acc[4]);
            acc[5] = __fmaf_rn(f, w1.y, acc[5]);
            acc[6] = __fmaf_rn(f, w1.z, acc[6]);
            acc[7] = __fmaf_rn(f, w1.w, acc[7]);
            acc[8] = __fmaf_rn(f, w2v.x, acc[8]);
            acc[9] = __fmaf_rn(f, w2v.y, acc[9]);
        }
    }

    float* out = g_cur2 + (size_t)row * NOUT;
#pragma unroll
    for (int o = 0; o < NOUT; o++)
        out[o] = __fadd_rn(acc[o], __ldg(&b2[o]));
}

// ---------------------------------------------------------------------------
// rec2: layer-2 recurrence + outputs [spk_rec | mem_rec].
// ---------------------------------------------------------------------------
__global__ void __launch_bounds__(256)
rec2_kernel(float* __restrict__ out)
{
    const int idx = blockIdx.x * blockDim.x + threadIdx.x;
    if (idx >= BATCH * NOUT) return;

    float mem = 0.f;
#pragma unroll
    for (int t = 0; t < NUM_STEPS; t++) {
        const float c   = g_cur2[(size_t)t * (BATCH * NOUT) + idx];
        const float rst = (mem > THRESH) ? THRESH : 0.f;
        mem = __fsub_rn(__fadd_rn(__fmul_rn(BETA, mem), c), rst);
        const float spk = (mem > THRESH) ? 1.f : 0.f;
        out[(size_t)t * (BATCH * NOUT) + idx] = spk;
        out[(size_t)NUM_STEPS * BATCH * NOUT + (size_t)t * (BATCH * NOUT) + idx] = mem;
    }
}

// ---------------------------------------------------------------------------
extern "C" void kernel_launch(void* const* d_in, const int* in_sizes, int n_in,
                              void* d_out, int out_size)
{
    const float* x  = (const float*)d_in[0];
    const float* W1 = (const float*)d_in[1];
    const float* b1 = (const float*)d_in[2];
    const float* W2 = (const float*)d_in[3];
    const float* b2 = (const float*)d_in[4];
    float* out = (float*)d_out;

    const int xs_bytes = NUM_STEPS * XLD * (int)sizeof(float);
    cudaFuncSetAttribute(fixup_kernel,
                         cudaFuncAttributeMaxDynamicSharedMemorySize, xs_bytes);

    splitx_kernel<<<MTOT, 256>>>(x);
    splitw_kernel<<<1024, 256>>>(W1);

    dim3 g1(8, MTOT / 128);
    gemm1t_kernel<<<g1, 256>>>(b1);

    flagrec_kernel<<<(BATCH * 32) / 8, 256>>>();

    fixup_kernel<<<BATCH, 256, xs_bytes>>>(x, W1, b1);

    gemm2_kernel<<<MTOT / 256, 256>>>(W2, b2);

    rec2_kernel<<<(BATCH * NOUT + 255) / 256, 256>>>(out);
}